// round 6
// baseline (speedup 1.0000x reference)
#include <cuda_runtime.h>
#include <cuda_bf16.h>

#define H 2048
#define W 128
#define D 200
#define V 45
#define XN (H + W)          // 2176
#define NB 592              // 148 SMs * 4 resident blocks
#define NT 256
#define GW_TOTAL (NB * 8)   // 4736 warps
#define XF4 (XN / 4)        // 544
#define HF4 (H / 4)         // 512
#define NIH (3 * H)         // 6144 ih dot rows
#define NHH (3 * H)         // 6144 hh dot rows
// stage-1 hh workers: blocks 19..591 -> warps [152, 4736)
#define HH_W0 152
#define HH_NW (GW_TOTAL - HH_W0)   // 4584

// ---------------- scratch (no allocs allowed) ----------------
__device__ __align__(16) float g_ctrl[4];
__device__ __align__(16) float g_sin[W];
__device__ __align__(16) float g_x[XN];      // [emb[inp] (H) | stack_top (W)]
__device__ __align__(16) float g_gi[3 * H];
__device__ __align__(16) float g_gh[3 * H];
__device__ __align__(16) float g_hnew[H];
__device__ unsigned g_bar_count = 0;
__device__ volatile unsigned g_bar_gen = 0;

__device__ __forceinline__ float dot4(const float4 a, const float4 b) {
    return a.x * b.x + a.y * b.y + a.z * b.z + a.w * b.w;
}

__device__ __forceinline__ float warpReduce(float v) {
#pragma unroll
    for (int o = 16; o > 0; o >>= 1) v += __shfl_down_sync(0xffffffffu, v, o);
    return v;
}

// Sense-reversing grid barrier; all NB blocks resident (launch_bounds(256,4)).
__device__ __forceinline__ void gridBarrier() {
    __syncthreads();
    if (threadIdx.x == 0) {
        __threadfence();
        unsigned my = g_bar_gen;
        if (atomicAdd(&g_bar_count, 1u) == NB - 1) {
            g_bar_count = 0;
            __threadfence();
            g_bar_gen = my + 1;
        } else {
            while (g_bar_gen == my) { }
            __threadfence();
        }
    }
    __syncthreads();
}

// Fully-unrolled warp dot: N4 float4 terms, lane-strided by 32.
// Plain cached loads -> weights stay L2-resident across graph replays.
template<int N4>
__device__ __forceinline__ float dotRow(const float4* __restrict__ w4,
                                        const float4* __restrict__ xv, int lane) {
    float s0 = 0.f, s1 = 0.f, s2 = 0.f, s3 = 0.f;
#pragma unroll
    for (int g = 0; g < N4 / 128; g++) {
        int i = lane + g * 128;
        s0 += dot4(w4[i],      xv[i]);
        s1 += dot4(w4[i + 32], xv[i + 32]);
        s2 += dot4(w4[i + 64], xv[i + 64]);
        s3 += dot4(w4[i + 96], xv[i + 96]);
    }
    if (N4 % 128) {
        int i = lane + (N4 / 128) * 128;
        s0 += dot4(w4[i], xv[i]);
    }
    return warpReduce((s0 + s1) + (s2 + s3));
}

__global__ void __launch_bounds__(NT, 4) fused(
        const int*   __restrict__ inp,
        const float* __restrict__ h,
        const float* __restrict__ stack,
        const float* __restrict__ emb,
        const float* __restrict__ ctrl_W, const float* __restrict__ ctrl_b,
        const float* __restrict__ sin_W,  const float* __restrict__ sin_b,
        const float* __restrict__ w_ih,   const float* __restrict__ w_hh,
        const float* __restrict__ b_ih,   const float* __restrict__ b_hh,
        const float* __restrict__ dec_W,  const float* __restrict__ dec_b,
        float* __restrict__ out)
{
    const int tid = threadIdx.x;
    const int warpId = tid >> 5, lane = tid & 31;
    const int b = blockIdx.x;
    const int gw = b * 8 + warpId;

    __shared__ __align__(16) float4 xs[XF4 + HF4];   // [x | h], 16.9 KB

    // Stage h into shared immediately (input, always ready).
    {
        const float4* gh4 = (const float4*)h;
        for (int i = tid; i < HF4; i += NT) xs[XF4 + i] = gh4[i];
    }
    __syncthreads();
    const float4* hs = xs + XF4;

    // ========== Stage 1: ctrl/sin/emb  ||  all w_hh dot rows ===============
    if (gw < 131) {
        const float* wrow = (gw < 3) ? (ctrl_W + (size_t)gw * H)
                                     : (sin_W + (size_t)(gw - 3) * H);
        float s = dotRow<HF4>((const float4*)wrow, hs, lane);
        if (lane == 0) {
            if (gw < 3) g_ctrl[gw] = s + ctrl_b[gw];
            else        g_sin[gw - 3] = tanhf(s + sin_b[gw - 3]);
        }
    } else if (b == 17 || b == 18) {         // emb[inp] -> g_x[0:H), 512 float4
        int i4 = (b - 17) * NT + tid;
        if (i4 < HF4)
            ((float4*)g_x)[i4] = ((const float4*)emb)[(size_t)inp[0] * HF4 + i4];
    } else if (gw >= HH_W0) {                // w_hh streaming (needs only h)
        unsigned wi = gw - HH_W0;
        unsigned t0 = (wi * (unsigned)NHH) / HH_NW;
        unsigned t1 = ((wi + 1) * (unsigned)NHH) / HH_NW;
        for (unsigned t = t0; t < t1; t++) {
            const float4* w4 = ((const float4*)w_hh) + (size_t)t * HF4;
            float s = dotRow<HF4>(w4, hs, lane);
            if (lane == 0) g_gh[t] = s + b_hh[t];
        }
    }
    gridBarrier();

    // ========== Stage 2: softmax + stack update ============================
    if (b < 25) {
        float l0 = g_ctrl[0], l1 = g_ctrl[1], l2 = g_ctrl[2];
        float m = fmaxf(l0, fmaxf(l1, l2));
        float e0 = expf(l0 - m), e1 = expf(l1 - m), e2 = expf(l2 - m);
        float inv = 1.0f / (e0 + e1 + e2);
        float c0 = e0 * inv, c1 = e1 * inv, c2 = e2 * inv;

        const float4* s4   = (const float4*)stack;
        const float4* sin4 = (const float4*)g_sin;
        float* out_stack = out + V + H;      // only 4B aligned -> scalar stores

        int i4 = b * NT + tid;               // < 6400
        if (i4 < (D * W) / 4) {
            const int RW4 = W / 4;
            int d = i4 / RW4, c = i4 - d * RW4;
            float4 cur  = s4[i4];
            float4 up   = (d == 0)     ? sin4[c] : s4[i4 - RW4];
            float4 down = (d == D - 1) ? make_float4(0.f, 0.f, 0.f, 0.f) : s4[i4 + RW4];
            float4 nv;
            nv.x = c2 * cur.x + c0 * up.x + c1 * down.x;
            nv.y = c2 * cur.y + c0 * up.y + c1 * down.y;
            nv.z = c2 * cur.z + c0 * up.z + c1 * down.z;
            nv.w = c2 * cur.w + c0 * up.w + c1 * down.w;
            int e = i4 * 4;
            out_stack[e + 0] = nv.x;
            out_stack[e + 1] = nv.y;
            out_stack[e + 2] = nv.z;
            out_stack[e + 3] = nv.w;
            if (d == 0) ((float4*)g_x)[HF4 + c] = nv;   // stack_top tail of x
        }
    }
    gridBarrier();

    // ========== Stage 3: all w_ih dot rows (need x) ========================
    {
        // stage x into shared
        const float4* gx4 = (const float4*)g_x;
        for (int i = tid; i < XF4; i += NT) xs[i] = gx4[i];
        __syncthreads();

        unsigned t0 = ((unsigned)gw * (unsigned)NIH) / GW_TOTAL;
        unsigned t1 = ((unsigned)(gw + 1) * (unsigned)NIH) / GW_TOTAL;
        for (unsigned t = t0; t < t1; t++) {
            const float4* w4 = ((const float4*)w_ih) + (size_t)t * XF4;
            float s = dotRow<XF4>(w4, xs, lane);
            if (lane == 0) g_gi[t] = s + b_ih[t];
        }
    }
    gridBarrier();

    // ========== Stage 4: GRU gate math -> h_new ============================
    if (b < 8) {
        int j = b * NT + tid;                // < 2048
        float ir = g_gi[j], iz = g_gi[j + H], in_ = g_gi[j + 2 * H];
        float hr = g_gh[j], hz = g_gh[j + H], hn = g_gh[j + 2 * H];
        float r = 1.0f / (1.0f + expf(-(ir + hr)));
        float z = 1.0f / (1.0f + expf(-(iz + hz)));
        float n = tanhf(in_ + r * hn);
        float hnew = (1.0f - z) * n + z * h[j];
        g_hnew[j] = hnew;
        out[V + j] = hnew;
    }
    gridBarrier();

    // ========== Stage 5: decoder GEMV (45 warp dots) =======================
    if (gw < V) {
        const float4* w4 = (const float4*)(dec_W + (size_t)gw * H);
        const float4* h4 = (const float4*)g_hnew;
        float s = 0.0f;
#pragma unroll
        for (int g = 0; g < 16; g++) {
            int i = lane + g * 32;
            s += dot4(w4[i], h4[i]);
        }
        s = warpReduce(s);
        if (lane == 0) out[gw] = s + dec_b[gw];
    }
}

// ---------------- launch ----------------
extern "C" void kernel_launch(void* const* d_in, const int* in_sizes, int n_in,
                              void* d_out, int out_size) {
    const int*   inp    = (const int*)  d_in[0];
    const float* hidden = (const float*)d_in[1];
    const float* stack  = (const float*)d_in[2];
    const float* emb    = (const float*)d_in[3];
    const float* ctrl_W = (const float*)d_in[4];
    const float* ctrl_b = (const float*)d_in[5];
    const float* sin_W  = (const float*)d_in[6];
    const float* sin_b  = (const float*)d_in[7];
    const float* w_ih   = (const float*)d_in[8];
    const float* w_hh   = (const float*)d_in[9];
    const float* b_ih   = (const float*)d_in[10];
    const float* b_hh   = (const float*)d_in[11];
    const float* dec_W  = (const float*)d_in[12];
    const float* dec_b  = (const float*)d_in[13];
    float* out = (float*)d_out;
    // out layout: [0,V) logits | [V, V+H) h_new | [V+H, V+H+D*W) new_stack

    fused<<<NB, NT>>>(inp, hidden, stack, emb, ctrl_W, ctrl_b, sin_W, sin_b,
                      w_ih, w_hh, b_ih, b_hh, dec_W, dec_b, out);
}

// round 7
// speedup vs baseline: 1.4192x; 1.4192x over previous
#include <cuda_runtime.h>
#include <cuda_bf16.h>

#define H 2048
#define W 128
#define D 200
#define V 45
#define XN (H + W)          // 2176
#define NB 592              // 148 SMs * 4 resident blocks
#define NT 256
#define GW_TOTAL (NB * 8)   // 4736 warps
#define XF4 (XN / 4)        // 544
#define HF4 (H / 4)         // 512
#define NIH (3 * H)         // 6144 ih dot rows
#define NHH (3 * H)         // 6144 hh dot rows
// stage-1 hh workers: blocks 19..591 -> warps [152, 4736)
#define HH_W0 152
#define HH_NW (GW_TOTAL - HH_W0)   // 4584

// ---------------- scratch (no allocs allowed) ----------------
__device__ __align__(16) float g_ctrl[4];
__device__ __align__(16) float g_sin[W];
__device__ __align__(16) float g_x[XN];      // [emb[inp] (H) | stack_top (W)]
__device__ __align__(16) float g_gi[3 * H];
__device__ __align__(16) float g_gh[3 * H];
__device__ __align__(16) float g_hnew[H];
__device__ unsigned g_bar_count = 0;
__device__ volatile unsigned g_bar_gen = 0;

__device__ __forceinline__ float dot4(const float4 a, const float4 b) {
    return a.x * b.x + a.y * b.y + a.z * b.z + a.w * b.w;
}

__device__ __forceinline__ float warpReduce(float v) {
#pragma unroll
    for (int o = 16; o > 0; o >>= 1) v += __shfl_down_sync(0xffffffffu, v, o);
    return v;
}

// Sense-reversing grid barrier; all NB blocks resident (launch_bounds(256,4)).
__device__ __forceinline__ void gridBarrier() {
    __syncthreads();
    if (threadIdx.x == 0) {
        __threadfence();
        unsigned my = g_bar_gen;
        if (atomicAdd(&g_bar_count, 1u) == NB - 1) {
            g_bar_count = 0;
            __threadfence();
            g_bar_gen = my + 1;
        } else {
            while (g_bar_gen == my) { }
            __threadfence();
        }
    }
    __syncthreads();
}

// Warp dot: N4 float4 terms, lane-strided. 4-wide load batches (MLP=4),
// rolled loop (low regs), __ldcs evict-first for streamed weights.
template<int N4>
__device__ __forceinline__ float dotRow(const float4* __restrict__ w4,
                                        const float4* __restrict__ xv, int lane) {
    float s0 = 0.f, s1 = 0.f, s2 = 0.f, s3 = 0.f;
    int i = lane;
#pragma unroll 1
    for (int g = 0; g < N4 / 128; g++, i += 128) {
        s0 += dot4(__ldcs(&w4[i]),      xv[i]);
        s1 += dot4(__ldcs(&w4[i + 32]), xv[i + 32]);
        s2 += dot4(__ldcs(&w4[i + 64]), xv[i + 64]);
        s3 += dot4(__ldcs(&w4[i + 96]), xv[i + 96]);
    }
    if (N4 % 128) s0 += dot4(__ldcs(&w4[i]), xv[i]);
    return warpReduce((s0 + s1) + (s2 + s3));
}

__global__ void __launch_bounds__(NT, 4) fused(
        const int*   __restrict__ inp,
        const float* __restrict__ h,
        const float* __restrict__ stack,
        const float* __restrict__ emb,
        const float* __restrict__ ctrl_W, const float* __restrict__ ctrl_b,
        const float* __restrict__ sin_W,  const float* __restrict__ sin_b,
        const float* __restrict__ w_ih,   const float* __restrict__ w_hh,
        const float* __restrict__ b_ih,   const float* __restrict__ b_hh,
        const float* __restrict__ dec_W,  const float* __restrict__ dec_b,
        float* __restrict__ out)
{
    const int tid = threadIdx.x;
    const int warpId = tid >> 5, lane = tid & 31;
    const int b = blockIdx.x;
    const int gw = b * 8 + warpId;

    __shared__ __align__(16) float4 xs[XF4 + HF4];   // [x | h], 16.9 KB

    // Stage h into shared immediately (input, always ready).
    {
        const float4* gh4 = (const float4*)h;
        for (int i = tid; i < HF4; i += NT) xs[XF4 + i] = gh4[i];
    }
    __syncthreads();
    const float4* hs = xs + XF4;

    // ========== Stage 1: ctrl/sin/emb  ||  all w_hh dot rows ===============
    if (gw < 131) {
        const float* wrow = (gw < 3) ? (ctrl_W + (size_t)gw * H)
                                     : (sin_W + (size_t)(gw - 3) * H);
        float s = dotRow<HF4>((const float4*)wrow, hs, lane);
        if (lane == 0) {
            if (gw < 3) g_ctrl[gw] = s + ctrl_b[gw];
            else        g_sin[gw - 3] = tanhf(s + sin_b[gw - 3]);
        }
    } else if (b == 17 || b == 18) {         // emb[inp] -> g_x[0:H), 512 float4
        int i4 = (b - 17) * NT + tid;
        if (i4 < HF4)
            ((float4*)g_x)[i4] = ((const float4*)emb)[(size_t)inp[0] * HF4 + i4];
    } else if (gw >= HH_W0) {                // w_hh streaming (needs only h)
        unsigned wi = gw - HH_W0;
        unsigned t0 = (wi * (unsigned)NHH) / HH_NW;
        unsigned t1 = ((wi + 1) * (unsigned)NHH) / HH_NW;
        for (unsigned t = t0; t < t1; t++) {
            const float4* w4 = ((const float4*)w_hh) + (size_t)t * HF4;
            float s = dotRow<HF4>(w4, hs, lane);
            if (lane == 0) g_gh[t] = s + b_hh[t];
        }
    }
    gridBarrier();

    // ========== Stage 2: softmax + stack update ============================
    if (b < 25) {
        float l0 = g_ctrl[0], l1 = g_ctrl[1], l2 = g_ctrl[2];
        float m = fmaxf(l0, fmaxf(l1, l2));
        float e0 = expf(l0 - m), e1 = expf(l1 - m), e2 = expf(l2 - m);
        float inv = 1.0f / (e0 + e1 + e2);
        float c0 = e0 * inv, c1 = e1 * inv, c2 = e2 * inv;

        const float4* s4   = (const float4*)stack;
        const float4* sin4 = (const float4*)g_sin;
        float* out_stack = out + V + H;      // only 4B aligned -> scalar stores

        int i4 = b * NT + tid;               // < 6400
        if (i4 < (D * W) / 4) {
            const int RW4 = W / 4;
            int d = i4 / RW4, c = i4 - d * RW4;
            float4 cur  = s4[i4];
            float4 up   = (d == 0)     ? sin4[c] : s4[i4 - RW4];
            float4 down = (d == D - 1) ? make_float4(0.f, 0.f, 0.f, 0.f) : s4[i4 + RW4];
            float4 nv;
            nv.x = c2 * cur.x + c0 * up.x + c1 * down.x;
            nv.y = c2 * cur.y + c0 * up.y + c1 * down.y;
            nv.z = c2 * cur.z + c0 * up.z + c1 * down.z;
            nv.w = c2 * cur.w + c0 * up.w + c1 * down.w;
            int e = i4 * 4;
            out_stack[e + 0] = nv.x;
            out_stack[e + 1] = nv.y;
            out_stack[e + 2] = nv.z;
            out_stack[e + 3] = nv.w;
            if (d == 0) ((float4*)g_x)[HF4 + c] = nv;   // stack_top tail of x
        }
    }
    gridBarrier();

    // ========== Stage 3: all w_ih dot rows (need x) ========================
    {
        // stage x into shared
        const float4* gx4 = (const float4*)g_x;
        for (int i = tid; i < XF4; i += NT) xs[i] = gx4[i];
        __syncthreads();

        unsigned t0 = ((unsigned)gw * (unsigned)NIH) / GW_TOTAL;
        unsigned t1 = ((unsigned)(gw + 1) * (unsigned)NIH) / GW_TOTAL;
        for (unsigned t = t0; t < t1; t++) {
            const float4* w4 = ((const float4*)w_ih) + (size_t)t * XF4;
            float s = dotRow<XF4>(w4, xs, lane);
            if (lane == 0) g_gi[t] = s + b_ih[t];
        }
    }
    gridBarrier();

    // ========== Stage 4: GRU gate math -> h_new ============================
    if (b < 8) {
        int j = b * NT + tid;                // < 2048
        float ir = g_gi[j], iz = g_gi[j + H], in_ = g_gi[j + 2 * H];
        float hr = g_gh[j], hz = g_gh[j + H], hn = g_gh[j + 2 * H];
        float r = 1.0f / (1.0f + expf(-(ir + hr)));
        float z = 1.0f / (1.0f + expf(-(iz + hz)));
        float n = tanhf(in_ + r * hn);
        float hnew = (1.0f - z) * n + z * h[j];
        g_hnew[j] = hnew;
        out[V + j] = hnew;
    }
    gridBarrier();

    // ========== Stage 5: decoder GEMV (45 warp dots) =======================
    if (gw < V) {
        const float4* w4 = (const float4*)(dec_W + (size_t)gw * H);
        const float4* h4 = (const float4*)g_hnew;
        float s0 = 0.f, s1 = 0.f, s2 = 0.f, s3 = 0.f;
        int i = lane;
#pragma unroll 1
        for (int g = 0; g < 4; g++, i += 128) {
            s0 += dot4(w4[i],      h4[i]);
            s1 += dot4(w4[i + 32], h4[i + 32]);
            s2 += dot4(w4[i + 64], h4[i + 64]);
            s3 += dot4(w4[i + 96], h4[i + 96]);
        }
        float s = warpReduce((s0 + s1) + (s2 + s3));
        if (lane == 0) out[gw] = s + dec_b[gw];
    }
}

// ---------------- launch ----------------
extern "C" void kernel_launch(void* const* d_in, const int* in_sizes, int n_in,
                              void* d_out, int out_size) {
    const int*   inp    = (const int*)  d_in[0];
    const float* hidden = (const float*)d_in[1];
    const float* stack  = (const float*)d_in[2];
    const float* emb    = (const float*)d_in[3];
    const float* ctrl_W = (const float*)d_in[4];
    const float* ctrl_b = (const float*)d_in[5];
    const float* sin_W  = (const float*)d_in[6];
    const float* sin_b  = (const float*)d_in[7];
    const float* w_ih   = (const float*)d_in[8];
    const float* w_hh   = (const float*)d_in[9];
    const float* b_ih   = (const float*)d_in[10];
    const float* b_hh   = (const float*)d_in[11];
    const float* dec_W  = (const float*)d_in[12];
    const float* dec_b  = (const float*)d_in[13];
    float* out = (float*)d_out;
    // out layout: [0,V) logits | [V, V+H) h_new | [V+H, V+H+D*W) new_stack

    fused<<<NB, NT>>>(inp, hidden, stack, emb, ctrl_W, ctrl_b, sin_W, sin_b,
                      w_ih, w_hh, b_ih, b_hh, dec_W, dec_b, out);
}

// round 8
// speedup vs baseline: 1.4966x; 1.0545x over previous
#include <cuda_runtime.h>
#include <cuda_bf16.h>

#define H 2048
#define W 128
#define D 200
#define V 45
#define XN (H + W)          // 2176
#define NB 592              // 148 SMs * 4 resident blocks
#define NT 256
#define GW_TOTAL (NB * 8)   // 4736 warps
#define XF4 (XN / 4)        // 544 = 4 * 136
#define HF4 (H / 4)         // 512 = 4 * 128
#define NROWS (3 * H)       // 6144 rows each for ih / hh
#define NUNITS (NROWS * 4)  // 24576 quarter-row units
#define NWORK 4096          // 4096 warps * 6 units = 24576 exactly
// stage-1 hh workers occupy gw in [HHW0, HHW0+NWORK)
#define HHW0 160

// ---------------- scratch (no allocs allowed) ----------------
__device__ __align__(16) float g_ctrl[4];
__device__ __align__(16) float g_sin[W];
__device__ __align__(16) float g_x[XN];      // [emb[inp] (H) | stack_top (W)]
__device__ __align__(16) float g_giq[NUNITS];   // ih quarter partials
__device__ __align__(16) float g_ghq[NUNITS];   // hh quarter partials
__device__ __align__(16) float g_hnew[H];
__device__ unsigned g_bar_count = 0;
__device__ volatile unsigned g_bar_gen = 0;

__device__ __forceinline__ float dot4(const float4 a, const float4 b) {
    return a.x * b.x + a.y * b.y + a.z * b.z + a.w * b.w;
}

__device__ __forceinline__ float warpReduce(float v) {
#pragma unroll
    for (int o = 16; o > 0; o >>= 1) v += __shfl_down_sync(0xffffffffu, v, o);
    return v;
}

// Sense-reversing grid barrier; all NB blocks resident (launch_bounds(256,4)).
__device__ __forceinline__ void gridBarrier() {
    __syncthreads();
    if (threadIdx.x == 0) {
        __threadfence();
        unsigned my = g_bar_gen;
        if (atomicAdd(&g_bar_count, 1u) == NB - 1) {
            g_bar_count = 0;
            __threadfence();
            g_bar_gen = my + 1;
        } else {
            while (g_bar_gen == my) { }
            __threadfence();
        }
    }
    __syncthreads();
}

// Quarter-row dot, 128 float4 (hh): 4 batched evict-first loads, MLP=4.
__device__ __forceinline__ float unitDotH(const float4* __restrict__ w,
                                          const float4* __restrict__ xv, int lane) {
    float s = dot4(__ldcs(&w[lane]),      xv[lane])
            + dot4(__ldcs(&w[lane + 32]), xv[lane + 32])
            + dot4(__ldcs(&w[lane + 64]), xv[lane + 64])
            + dot4(__ldcs(&w[lane + 96]), xv[lane + 96]);
    return warpReduce(s);
}

// Quarter-row dot, 136 float4 (ih): 4 batches + predicated 5th for lanes<8.
__device__ __forceinline__ float unitDotX(const float4* __restrict__ w,
                                          const float4* __restrict__ xv, int lane) {
    float s = dot4(__ldcs(&w[lane]),      xv[lane])
            + dot4(__ldcs(&w[lane + 32]), xv[lane + 32])
            + dot4(__ldcs(&w[lane + 64]), xv[lane + 64])
            + dot4(__ldcs(&w[lane + 96]), xv[lane + 96]);
    if (lane < 8) s += dot4(__ldcs(&w[lane + 128]), xv[lane + 128]);
    return warpReduce(s);
}

__global__ void __launch_bounds__(NT, 4) fused(
        const int*   __restrict__ inp,
        const float* __restrict__ h,
        const float* __restrict__ stack,
        const float* __restrict__ emb,
        const float* __restrict__ ctrl_W, const float* __restrict__ ctrl_b,
        const float* __restrict__ sin_W,  const float* __restrict__ sin_b,
        const float* __restrict__ w_ih,   const float* __restrict__ w_hh,
        const float* __restrict__ b_ih,   const float* __restrict__ b_hh,
        const float* __restrict__ dec_W,  const float* __restrict__ dec_b,
        float* __restrict__ out)
{
    const int tid = threadIdx.x;
    const int warpId = tid >> 5, lane = tid & 31;
    const int b = blockIdx.x;
    const int gw = b * 8 + warpId;

    __shared__ __align__(16) float4 xs[XF4 + HF4];   // [x | h], 16.9 KB

    // Stage h into shared immediately (input, always ready).
    {
        const float4* gh4 = (const float4*)h;
        for (int i = tid; i < HF4; i += NT) xs[XF4 + i] = gh4[i];
    }
    __syncthreads();
    const float4* hs = xs + XF4;

    // ===== Stage 1: ctrl/sin (131 warps) || emb (16 warps) || hh quarters ==
    if (gw < 131) {
        const float* wrow = (gw < 3) ? (ctrl_W + (size_t)gw * H)
                                     : (sin_W + (size_t)(gw - 3) * H);
        const float4* w4 = (const float4*)wrow;
        float s0 = 0.f, s1 = 0.f, s2 = 0.f, s3 = 0.f;
        int i = lane;
#pragma unroll 1
        for (int g = 0; g < 4; g++, i += 128) {
            s0 += dot4(w4[i],      hs[i]);
            s1 += dot4(w4[i + 32], hs[i + 32]);
            s2 += dot4(w4[i + 64], hs[i + 64]);
            s3 += dot4(w4[i + 96], hs[i + 96]);
        }
        float s = warpReduce((s0 + s1) + (s2 + s3));
        if (lane == 0) {
            if (gw < 3) g_ctrl[gw] = s + ctrl_b[gw];
            else        g_sin[gw - 3] = tanhf(s + sin_b[gw - 3]);
        }
    } else if (gw >= GW_TOTAL - 16) {        // emb[inp] -> g_x[0:H), 512 f4
        int i4 = (gw - (GW_TOTAL - 16)) * 32 + lane;
        ((float4*)g_x)[i4] = ((const float4*)emb)[(size_t)inp[0] * HF4 + i4];
    } else if (gw >= HHW0 && gw < HHW0 + NWORK) {
        int u = (gw - HHW0) * 6;
#pragma unroll 1
        for (int k = 0; k < 6; k++, u++) {
            int r = u >> 2, q = u & 3;
            const float4* w = ((const float4*)w_hh) + (size_t)r * HF4 + q * 128;
            float s = unitDotH(w, hs + q * 128, lane);
            if (lane == 0) g_ghq[u] = s;
        }
    }
    gridBarrier();

    // ===== Stage 2: softmax + stack update =================================
    if (b < 25) {
        float l0 = g_ctrl[0], l1 = g_ctrl[1], l2 = g_ctrl[2];
        float m = fmaxf(l0, fmaxf(l1, l2));
        float e0 = expf(l0 - m), e1 = expf(l1 - m), e2 = expf(l2 - m);
        float inv = 1.0f / (e0 + e1 + e2);
        float c0 = e0 * inv, c1 = e1 * inv, c2 = e2 * inv;

        const float4* s4   = (const float4*)stack;
        const float4* sin4 = (const float4*)g_sin;
        float* out_stack = out + V + H;      // only 4B aligned -> scalar stores

        int i4 = b * NT + tid;               // < 6400
        if (i4 < (D * W) / 4) {
            const int RW4 = W / 4;
            int d = i4 / RW4, c = i4 - d * RW4;
            float4 cur  = s4[i4];
            float4 up   = (d == 0)     ? sin4[c] : s4[i4 - RW4];
            float4 down = (d == D - 1) ? make_float4(0.f, 0.f, 0.f, 0.f) : s4[i4 + RW4];
            float4 nv;
            nv.x = c2 * cur.x + c0 * up.x + c1 * down.x;
            nv.y = c2 * cur.y + c0 * up.y + c1 * down.y;
            nv.z = c2 * cur.z + c0 * up.z + c1 * down.z;
            nv.w = c2 * cur.w + c0 * up.w + c1 * down.w;
            int e = i4 * 4;
            out_stack[e + 0] = nv.x;
            out_stack[e + 1] = nv.y;
            out_stack[e + 2] = nv.z;
            out_stack[e + 3] = nv.w;
            if (d == 0) ((float4*)g_x)[HF4 + c] = nv;   // stack_top tail of x
        }
    }
    gridBarrier();

    // ===== Stage 3: ih quarter units (need x) ==============================
    {
        const float4* gx4 = (const float4*)g_x;
        for (int i = tid; i < XF4; i += NT) xs[i] = gx4[i];
        __syncthreads();

        if (gw < NWORK) {
            int u = gw * 6;
#pragma unroll 1
            for (int k = 0; k < 6; k++, u++) {
                int r = u >> 2, q = u & 3;
                const float4* w = ((const float4*)w_ih) + (size_t)r * XF4 + q * 136;
                float s = unitDotX(w, xs + q * 136, lane);
                if (lane == 0) g_giq[u] = s;
            }
        }
    }
    gridBarrier();

    // ===== Stage 4: sum quarters + GRU gate math -> h_new ==================
    if (b < 8) {
        int j = b * NT + tid;                // < 2048
        int r0 = j, r1 = j + H, r2 = j + 2 * H;
        float ir = g_giq[4*r0] + g_giq[4*r0+1] + g_giq[4*r0+2] + g_giq[4*r0+3] + b_ih[r0];
        float iz = g_giq[4*r1] + g_giq[4*r1+1] + g_giq[4*r1+2] + g_giq[4*r1+3] + b_ih[r1];
        float in_= g_giq[4*r2] + g_giq[4*r2+1] + g_giq[4*r2+2] + g_giq[4*r2+3] + b_ih[r2];
        float hr = g_ghq[4*r0] + g_ghq[4*r0+1] + g_ghq[4*r0+2] + g_ghq[4*r0+3] + b_hh[r0];
        float hz = g_ghq[4*r1] + g_ghq[4*r1+1] + g_ghq[4*r1+2] + g_ghq[4*r1+3] + b_hh[r1];
        float hn = g_ghq[4*r2] + g_ghq[4*r2+1] + g_ghq[4*r2+2] + g_ghq[4*r2+3] + b_hh[r2];
        float r = 1.0f / (1.0f + expf(-(ir + hr)));
        float z = 1.0f / (1.0f + expf(-(iz + hz)));
        float n = tanhf(in_ + r * hn);
        float hnew = (1.0f - z) * n + z * h[j];
        g_hnew[j] = hnew;
        out[V + j] = hnew;
    }
    gridBarrier();

    // ===== Stage 5: decoder GEMV (45 warp dots) ============================
    if (gw < V) {
        const float4* w4 = (const float4*)(dec_W + (size_t)gw * H);
        const float4* h4 = (const float4*)g_hnew;
        float s0 = 0.f, s1 = 0.f, s2 = 0.f, s3 = 0.f;
        int i = lane;
#pragma unroll 1
        for (int g = 0; g < 4; g++, i += 128) {
            s0 += dot4(w4[i],      h4[i]);
            s1 += dot4(w4[i + 32], h4[i + 32]);
            s2 += dot4(w4[i + 64], h4[i + 64]);
            s3 += dot4(w4[i + 96], h4[i + 96]);
        }
        float s = warpReduce((s0 + s1) + (s2 + s3));
        if (lane == 0) out[gw] = s + dec_b[gw];
    }
}

// ---------------- launch ----------------
extern "C" void kernel_launch(void* const* d_in, const int* in_sizes, int n_in,
                              void* d_out, int out_size) {
    const int*   inp    = (const int*)  d_in[0];
    const float* hidden = (const float*)d_in[1];
    const float* stack  = (const float*)d_in[2];
    const float* emb    = (const float*)d_in[3];
    const float* ctrl_W = (const float*)d_in[4];
    const float* ctrl_b = (const float*)d_in[5];
    const float* sin_W  = (const float*)d_in[6];
    const float* sin_b  = (const float*)d_in[7];
    const float* w_ih   = (const float*)d_in[8];
    const float* w_hh   = (const float*)d_in[9];
    const float* b_ih   = (const float*)d_in[10];
    const float* b_hh   = (const float*)d_in[11];
    const float* dec_W  = (const float*)d_in[12];
    const float* dec_b  = (const float*)d_in[13];
    float* out = (float*)d_out;
    // out layout: [0,V) logits | [V, V+H) h_new | [V+H, V+H+D*W) new_stack

    fused<<<NB, NT>>>(inp, hidden, stack, emb, ctrl_W, ctrl_b, sin_W, sin_b,
                      w_ih, w_hh, b_ih, b_hh, dec_W, dec_b, out);
}

// round 9
// speedup vs baseline: 1.7956x; 1.1998x over previous
#include <cuda_runtime.h>
#include <cuda_bf16.h>

#define H 2048
#define W 128
#define D 200
#define V 45
#define XN (H + W)          // 2176
#define NB 148              // one block per SM, all resident
#define NT 1024
#define GW_TOTAL (NB * 32)  // 4736 warps
#define XF4 (XN / 4)        // 544
#define HF4 (H / 4)         // 512
#define NIH (3 * H)         // 6144
#define NDOT (2 * 3 * H)    // 12288 dot rows (ih then hh)

// ---------------- scratch (no allocs allowed) ----------------
__device__ __align__(16) float g_ctrl[4];
__device__ __align__(16) float g_sin[W];
__device__ __align__(16) float g_x[XN];      // [emb[inp] (H) | stack_top (W)]
__device__ __align__(16) float g_gi[3 * H];
__device__ __align__(16) float g_gh[3 * H];
__device__ __align__(16) float g_hnew[H];
__device__ unsigned g_bar_count = 0;
__device__ volatile unsigned g_bar_gen = 0;

__device__ __forceinline__ float dot4(const float4 a, const float4 b) {
    return a.x * b.x + a.y * b.y + a.z * b.z + a.w * b.w;
}

__device__ __forceinline__ float warpReduce(float v) {
#pragma unroll
    for (int o = 16; o > 0; o >>= 1) v += __shfl_down_sync(0xffffffffu, v, o);
    return v;
}

// Sense-reversing grid barrier; all NB=148 blocks resident (1 per SM).
__device__ __forceinline__ void gridBarrier() {
    __syncthreads();
    if (threadIdx.x == 0) {
        __threadfence();
        unsigned my = g_bar_gen;
        if (atomicAdd(&g_bar_count, 1u) == NB - 1) {
            g_bar_count = 0;
            __threadfence();
            g_bar_gen = my + 1;
        } else {
            while (g_bar_gen == my) { }
            __threadfence();
        }
    }
    __syncthreads();
}

// Warp dot: N4 float4 terms, lane-strided. 8 loads in flight (MLP=8),
// rolled outer loop, __ldcs evict-first for streamed weights.
template<int N4>
__device__ __forceinline__ float dotRow(const float4* __restrict__ w,
                                        const float4* __restrict__ xv, int lane) {
    float s0 = 0.f, s1 = 0.f, s2 = 0.f, s3 = 0.f;
    int i = lane;
#pragma unroll 1
    for (int g = 0; g < N4 / 256; g++, i += 256) {
        float4 a0 = __ldcs(&w[i]);
        float4 a1 = __ldcs(&w[i + 32]);
        float4 a2 = __ldcs(&w[i + 64]);
        float4 a3 = __ldcs(&w[i + 96]);
        float4 a4 = __ldcs(&w[i + 128]);
        float4 a5 = __ldcs(&w[i + 160]);
        float4 a6 = __ldcs(&w[i + 192]);
        float4 a7 = __ldcs(&w[i + 224]);
        s0 += dot4(a0, xv[i])       + dot4(a4, xv[i + 128]);
        s1 += dot4(a1, xv[i + 32])  + dot4(a5, xv[i + 160]);
        s2 += dot4(a2, xv[i + 64])  + dot4(a6, xv[i + 192]);
        s3 += dot4(a3, xv[i + 96])  + dot4(a7, xv[i + 224]);
    }
    if (N4 % 256) s0 += dot4(__ldcs(&w[i]), xv[i]);   // 32-f4 remainder (ih)
    return warpReduce((s0 + s1) + (s2 + s3));
}

__global__ void __launch_bounds__(NT, 1) fused(
        const int*   __restrict__ inp,
        const float* __restrict__ h,
        const float* __restrict__ stack,
        const float* __restrict__ emb,
        const float* __restrict__ ctrl_W, const float* __restrict__ ctrl_b,
        const float* __restrict__ sin_W,  const float* __restrict__ sin_b,
        const float* __restrict__ w_ih,   const float* __restrict__ w_hh,
        const float* __restrict__ b_ih,   const float* __restrict__ b_hh,
        const float* __restrict__ dec_W,  const float* __restrict__ dec_b,
        float* __restrict__ out)
{
    const int tid = threadIdx.x;
    const int warpId = tid >> 5, lane = tid & 31;
    const int b = blockIdx.x;
    const int gw = b * 32 + warpId;

    __shared__ __align__(16) float4 xs[XF4 + HF4];   // [x | h], 16.9 KB

    // Stage h into shared immediately (input, always ready).
    {
        const float4* gh4 = (const float4*)h;
        for (int i = tid; i < HF4; i += NT) xs[XF4 + i] = gh4[i];
    }
    __syncthreads();
    const float4* hs = xs + XF4;

    // ========== Stage A: ctrl logits, sin rows, emb gather =================
    if (gw < 131) {
        const float* wrow = (gw < 3) ? (ctrl_W + (size_t)gw * H)
                                     : (sin_W + (size_t)(gw - 3) * H);
        float s = dotRow<HF4>((const float4*)wrow, hs, lane);
        if (lane == 0) {
            if (gw < 3) g_ctrl[gw] = s + ctrl_b[gw];
            else        g_sin[gw - 3] = tanhf(s + sin_b[gw - 3]);
        }
    } else if (b == 4 && warpId >= 8 && warpId < 24) {   // emb[inp] -> g_x[0:H)
        int i4 = (warpId - 8) * 32 + lane;               // 16 warps * 32 = 512 f4
        ((float4*)g_x)[i4] = ((const float4*)emb)[(size_t)inp[0] * HF4 + i4];
    }
    gridBarrier();

    // ========== Stage B: softmax + stack update ============================
    if (b < 7) {
        float l0 = g_ctrl[0], l1 = g_ctrl[1], l2 = g_ctrl[2];
        float m = fmaxf(l0, fmaxf(l1, l2));
        float e0 = expf(l0 - m), e1 = expf(l1 - m), e2 = expf(l2 - m);
        float inv = 1.0f / (e0 + e1 + e2);
        float c0 = e0 * inv, c1 = e1 * inv, c2 = e2 * inv;

        const float4* s4   = (const float4*)stack;
        const float4* sin4 = (const float4*)g_sin;
        float* out_stack = out + V + H;      // only 4B aligned -> scalar stores

        int i4 = b * NT + tid;               // < 6400
        if (i4 < (D * W) / 4) {
            const int RW4 = W / 4;
            int d = i4 / RW4, c = i4 - d * RW4;
            float4 cur  = s4[i4];
            float4 up   = (d == 0)     ? sin4[c] : s4[i4 - RW4];
            float4 down = (d == D - 1) ? make_float4(0.f, 0.f, 0.f, 0.f) : s4[i4 + RW4];
            float4 nv;
            nv.x = c2 * cur.x + c0 * up.x + c1 * down.x;
            nv.y = c2 * cur.y + c0 * up.y + c1 * down.y;
            nv.z = c2 * cur.z + c0 * up.z + c1 * down.z;
            nv.w = c2 * cur.w + c0 * up.w + c1 * down.w;
            int e = i4 * 4;
            out_stack[e + 0] = nv.x;
            out_stack[e + 1] = nv.y;
            out_stack[e + 2] = nv.z;
            out_stack[e + 3] = nv.w;
            if (d == 0) ((float4*)g_x)[HF4 + c] = nv;   // stack_top tail of x
        }
    }
    gridBarrier();

    // ========== Stage C: all 12288 GEMV dot-rows, flat =====================
    {
        // stage x into shared
        const float4* gx4 = (const float4*)g_x;
        for (int i = tid; i < XF4; i += NT) xs[i] = gx4[i];
        __syncthreads();

        unsigned t0 = ((unsigned)gw * NDOT) / GW_TOTAL;
        unsigned t1 = ((unsigned)(gw + 1) * NDOT) / GW_TOTAL;
        for (unsigned t = t0; t < t1; t++) {
            if (t < (unsigned)NIH) {
                const float4* w4 = ((const float4*)w_ih) + (size_t)t * XF4;
                float s = dotRow<XF4>(w4, xs, lane);
                if (lane == 0) g_gi[t] = s + b_ih[t];
            } else {
                unsigned r = t - NIH;
                const float4* w4 = ((const float4*)w_hh) + (size_t)r * HF4;
                float s = dotRow<HF4>(w4, hs, lane);
                if (lane == 0) g_gh[r] = s + b_hh[r];
            }
        }
    }
    gridBarrier();

    // ========== Stage C2: GRU gate math -> h_new ===========================
    if (b < 2) {
        int j = b * NT + tid;                // < 2048
        float ir = g_gi[j], iz = g_gi[j + H], in_ = g_gi[j + 2 * H];
        float hr = g_gh[j], hz = g_gh[j + H], hn = g_gh[j + 2 * H];
        float r = 1.0f / (1.0f + expf(-(ir + hr)));
        float z = 1.0f / (1.0f + expf(-(iz + hz)));
        float n = tanhf(in_ + r * hn);
        float hnew = (1.0f - z) * n + z * h[j];
        g_hnew[j] = hnew;
        out[V + j] = hnew;
    }
    gridBarrier();

    // ========== Stage D: decoder GEMV (45 warp dots) =======================
    if (gw < V) {
        const float4* w4 = (const float4*)(dec_W + (size_t)gw * H);
        float s = dotRow<HF4>(w4, (const float4*)g_hnew, lane);
        if (lane == 0) out[gw] = s + dec_b[gw];
    }
}

// ---------------- launch ----------------
extern "C" void kernel_launch(void* const* d_in, const int* in_sizes, int n_in,
                              void* d_out, int out_size) {
    const int*   inp    = (const int*)  d_in[0];
    const float* hidden = (const float*)d_in[1];
    const float* stack  = (const float*)d_in[2];
    const float* emb    = (const float*)d_in[3];
    const float* ctrl_W = (const float*)d_in[4];
    const float* ctrl_b = (const float*)d_in[5];
    const float* sin_W  = (const float*)d_in[6];
    const float* sin_b  = (const float*)d_in[7];
    const float* w_ih   = (const float*)d_in[8];
    const float* w_hh   = (const float*)d_in[9];
    const float* b_ih   = (const float*)d_in[10];
    const float* b_hh   = (const float*)d_in[11];
    const float* dec_W  = (const float*)d_in[12];
    const float* dec_b  = (const float*)d_in[13];
    float* out = (float*)d_out;
    // out layout: [0,V) logits | [V, V+H) h_new | [V+H, V+H+D*W) new_stack

    fused<<<NB, NT>>>(inp, hidden, stack, emb, ctrl_W, ctrl_b, sin_W, sin_b,
                      w_ih, w_hh, b_ih, b_hh, dec_W, dec_b, out);
}